// round 8
// baseline (speedup 1.0000x reference)
#include <cuda_runtime.h>
#include <cuda_bf16.h>
#include <math.h>
#include <stdint.h>

#define TT 4096
#define DD 768
#define EE 8
#define KX 2
#define HH 2048

typedef __nv_bfloat16 bf16;
typedef unsigned long long u64;
typedef unsigned int u32;

// ---------------- fp32 scratch ----------------
__device__ __align__(16) float g_gate[(size_t)EE*TT*HH];
__device__ __align__(16) float g_up  [(size_t)EE*TT*HH];
__device__ __align__(16) float g_eo  [(size_t)TT*EE*DD];
__device__ __align__(16) float g_qkv [(size_t)TT*EE*3*DD];
__device__ __align__(16) float g_attn[(size_t)TT*EE*DD];
__device__ __align__(16) float g_proj[(size_t)TT*EE*DD];
__device__ __align__(16) float g_ctx [(size_t)TT*EE*DD];
__device__ float g_rprobs[TT*EE];
__device__ int   g_tkidx[TT*KX];
__device__ float g_tkp  [TT*KX];
__device__ __align__(16) float g_sf [(size_t)TT*KX*DD];
__device__ __align__(16) float g_ao [(size_t)TT*KX*DD];
__device__ __align__(16) float g_h1 [(size_t)TT*KX*DD];
__device__ __align__(16) float g_ref[(size_t)TT*KX*DD];
__device__ __align__(16) float g_comb[(size_t)TT*DD];
__device__ float g_ent[TT];

// ---------------- bf16 split buffers ----------------
__device__ __align__(16) bf16 g_xS   [3*(size_t)TT*DD];
__device__ __align__(16) bf16 g_w1T  [3*(size_t)EE*HH*DD];
__device__ __align__(16) bf16 g_w3T  [3*(size_t)EE*HH*DD];
__device__ __align__(16) bf16 g_w2T  [3*(size_t)EE*DD*HH];
__device__ __align__(16) bf16 g_actS [3*(size_t)EE*TT*HH];
__device__ __align__(16) bf16 g_eoS  [3*(size_t)TT*EE*DD];
__device__ __align__(16) bf16 g_gS   [3*(size_t)TT*EE*DD];
__device__ __align__(16) bf16 g_rinS [3*(size_t)3*DD*DD];
__device__ __align__(16) bf16 g_routS[3*(size_t)DD*DD];
__device__ __align__(16) bf16 g_cinS [3*(size_t)3*DD*DD];
__device__ __align__(16) bf16 g_coutS[3*(size_t)DD*DD];
__device__ __align__(16) bf16 g_f1S  [3*(size_t)DD*DD];
__device__ __align__(16) bf16 g_f2S  [3*(size_t)DD*DD];
__device__ __align__(16) bf16 g_owS  [3*(size_t)DD*DD];

// ---------------- PTX helpers (sm_80+ only) ----------------
__device__ __forceinline__ u32 s2u(const void* p) {
    u32 a; asm("{ .reg .u64 t; cvta.to.shared.u64 t, %1; cvt.u32.u64 %0, t; }" : "=r"(a) : "l"(p));
    return a;
}
__device__ __forceinline__ void cpasync16(u32 saddr, const void* gaddr) {
    asm volatile("cp.async.cg.shared.global [%0], [%1], 16;" :: "r"(saddr), "l"(gaddr));
}
#define CP_COMMIT() asm volatile("cp.async.commit_group;" ::: "memory")
#define CP_WAIT(n)  asm volatile("cp.async.wait_group %0;" :: "n"(n) : "memory")

__device__ __forceinline__ void ldmx4(u32* r, u32 addr) {
    asm volatile("ldmatrix.sync.aligned.m8n8.x4.shared.b16 {%0,%1,%2,%3}, [%4];"
        : "=r"(r[0]), "=r"(r[1]), "=r"(r[2]), "=r"(r[3]) : "r"(addr));
}
__device__ __forceinline__ void mma16816(float* d, const u32* a, const u32* b) {
    asm volatile("mma.sync.aligned.m16n8k16.row.col.f32.bf16.bf16.f32 "
        "{%0,%1,%2,%3}, {%4,%5,%6,%7}, {%8,%9}, {%0,%1,%2,%3};"
        : "+f"(d[0]), "+f"(d[1]), "+f"(d[2]), "+f"(d[3])
        : "r"(a[0]), "r"(a[1]), "r"(a[2]), "r"(a[3]), "r"(b[0]), "r"(b[1]));
}

// smem layout inside a tile: off(row, seg16) = row*64 + ((seg16 ^ ((row>>1)&3))<<4)
__device__ __forceinline__ u32 swz(int row, int seg) {
    return (u32)((row << 6) + ((seg ^ ((row >> 1) & 3)) << 4));
}

// ---------------- exact 3-way bf16 split ----------------
__device__ __forceinline__ void split1(float x, bf16& h, bf16& m, bf16& l) {
    h = __float2bfloat16(x);
    float r = x - __bfloat162float(h);
    m = __float2bfloat16(r);
    l = __float2bfloat16(r - __bfloat162float(m));
}
__global__ void split3(const float* __restrict__ in, bf16* __restrict__ out,
                       size_t ss, size_t n) {
    for (size_t i = (size_t)blockIdx.x*blockDim.x + threadIdx.x; i < n;
         i += (size_t)gridDim.x*blockDim.x) {
        bf16 h, m, l; split1(in[i], h, m, l);
        out[i] = h; out[ss + i] = m; out[2*ss + i] = l;
    }
}
__global__ void split3_swiglu(const float* __restrict__ g, const float* __restrict__ u,
                              bf16* __restrict__ out, size_t ss, size_t n) {
    for (size_t i = (size_t)blockIdx.x*blockDim.x + threadIdx.x; i < n;
         i += (size_t)gridDim.x*blockDim.x) {
        float gv = g[i];
        float x = gv / (1.0f + expf(-gv)) * u[i];
        bf16 h, m, l; split1(x, h, m, l);
        out[i] = h; out[ss + i] = m; out[2*ss + i] = l;
    }
}
// transpose+split: (z): Kd x Nd fp32 -> (z): Nd x Kd bf16 x3 (split stride ss)
__global__ void tsplit(const float* __restrict__ in, bf16* __restrict__ out,
                       int Kd, int Nd, size_t ss) {
    __shared__ float t[32][33];
    const float* ip = in + (size_t)blockIdx.z * Kd * Nd;
    bf16* op = out + (size_t)blockIdx.z * Kd * Nd;
    int n0 = blockIdx.x * 32, k0 = blockIdx.y * 32;
    int tx = threadIdx.x, ty0 = threadIdx.y;
    for (int ty = ty0; ty < 32; ty += 8)
        t[ty][tx] = ip[(size_t)(k0 + ty) * Nd + n0 + tx];
    __syncthreads();
    for (int ty = ty0; ty < 32; ty += 8) {
        bf16 h, m, l; split1(t[tx][ty], h, m, l);
        size_t o = (size_t)(n0 + ty) * Kd + k0 + tx;
        op[o] = h; op[ss + o] = m; op[2*ss + o] = l;
    }
}

// ---------------- mma.sync split-fp32 GEMM ----------------
// D = sum_{6 pairs} A_s(MxKd bf16 K-major) @ B_s^T(NxKd bf16). grid (N/128,M/128,Z).
// K-chunk = 32; smem row stride 64B with XOR seg swizzle; 2 CTAs/SM.
#define TILE_B   8192               // 128 rows * 64B
#define STAGE_B  (6*TILE_B)         // 49152
#define TG_SMEM  (2*STAGE_B)        // 98304

__global__ void __launch_bounds__(256, 2) tgemm(
    const bf16* __restrict__ A, size_t aSS, size_t sA,
    const bf16* __restrict__ B, size_t bSS, size_t sB,
    int Kd,
    const float* __restrict__ bias, const float* __restrict__ resid,
    float* __restrict__ C, int ldc, size_t sC, int epi)   // epi: 0 none, 1 GELU
{
    extern __shared__ __align__(16) char smc[];
    const int tid = threadIdx.x, wid = tid >> 5, lane = tid & 31;
    const u32 sb = s2u(smc);
    const int rowBase = blockIdx.y << 7;
    const int colBase = blockIdx.x << 7;
    const bf16* Az = A + (size_t)blockIdx.z * sA;
    const bf16* Bz = B + (size_t)blockIdx.z * sB;
    C += (size_t)blockIdx.z * sC;

    const int warpM = wid >> 1;
    const int warpN = wid & 1;

    // ---- async chunk loader: 3072 x 16B per chunk (K-chunk = 32) ----
    auto loadChunk = [&](int c, int st) {
        const int k0 = c << 5;
        const u32 stBase = sb + (u32)st * STAGE_B;
        #pragma unroll
        for (int it = 0; it < 12; it++) {
            int idx = tid + (it << 8);            // 0..3071
            int mat   = idx / 1536;               // 0=A 1=B
            int r     = idx - mat * 1536;
            int split = r >> 9;                   // 0..2
            int rc    = r & 511;
            int row   = rc >> 2;                  // 0..127
            int seg   = rc & 3;                   // 16B segment
            const bf16* src = (mat == 0)
                ? Az + (size_t)split * aSS + (size_t)(rowBase + row) * Kd + k0 + (seg << 3)
                : Bz + (size_t)split * bSS + (size_t)(colBase + row) * Kd + k0 + (seg << 3);
            u32 dst = stBase + (u32)(mat * 3 + split) * TILE_B + swz(row, seg);
            cpasync16(dst, src);
        }
    };

    float acc[2][8][4];
    #pragma unroll
    for (int mt = 0; mt < 2; mt++)
        #pragma unroll
        for (int nt = 0; nt < 8; nt++)
            #pragma unroll
            for (int j = 0; j < 4; j++) acc[mt][nt][j] = 0.f;

    const int nc = Kd >> 5;
    loadChunk(0, 0); CP_COMMIT();

    const int aRowB = (warpM << 5) + (lane & 15);
    const int aSegH = lane >> 4;                             // 0/1
    const int bRowB = (warpN << 6) + ((lane >> 4) << 3) + (lane & 7);
    const int bSegH = (lane >> 3) & 1;

    for (int c = 0; c < nc; c++) {
        const int st = c & 1;
        if (c + 1 < nc) { loadChunk(c + 1, st ^ 1); CP_COMMIT(); CP_WAIT(1); }
        else CP_WAIT(0);
        __syncthreads();

        const u32 stBase = sb + (u32)st * STAGE_B;
        #pragma unroll
        for (int ks = 0; ks < 2; ks++) {
            const int segA = (ks << 1) | aSegH;
            const int segB = (ks << 1) | bSegH;
            u32 af[3][2][4];
            #pragma unroll
            for (int s = 0; s < 3; s++) {
                const u32 tb = stBase + (u32)s * TILE_B;
                #pragma unroll
                for (int mt = 0; mt < 2; mt++) {
                    int row = aRowB + (mt << 4);
                    ldmx4(af[s][mt], tb + swz(row, segA));
                }
            }
            u32 bf[8][2];
            // B split 0 (h): pairs (Ah,Bh),(Am,Bh),(Al,Bh)
            {
                const u32 tb = stBase + (u32)3 * TILE_B;
                #pragma unroll
                for (int p = 0; p < 4; p++) {
                    u32 t4[4];
                    int row = bRowB + (p << 4);
                    ldmx4(t4, tb + swz(row, segB));
                    bf[2*p][0] = t4[0]; bf[2*p][1] = t4[1];
                    bf[2*p+1][0] = t4[2]; bf[2*p+1][1] = t4[3];
                }
                #pragma unroll
                for (int s = 0; s < 3; s++)
                    #pragma unroll
                    for (int mt = 0; mt < 2; mt++)
                        #pragma unroll
                        for (int nt = 0; nt < 8; nt++)
                            mma16816(acc[mt][nt], af[s][mt], bf[nt]);
            }
            // B split 1 (m): pairs (Ah,Bm),(Am,Bm)
            {
                const u32 tb = stBase + (u32)4 * TILE_B;
                #pragma unroll
                for (int p = 0; p < 4; p++) {
                    u32 t4[4];
                    int row = bRowB + (p << 4);
                    ldmx4(t4, tb + swz(row, segB));
                    bf[2*p][0] = t4[0]; bf[2*p][1] = t4[1];
                    bf[2*p+1][0] = t4[2]; bf[2*p+1][1] = t4[3];
                }
                #pragma unroll
                for (int s = 0; s < 2; s++)
                    #pragma unroll
                    for (int mt = 0; mt < 2; mt++)
                        #pragma unroll
                        for (int nt = 0; nt < 8; nt++)
                            mma16816(acc[mt][nt], af[s][mt], bf[nt]);
            }
            // B split 2 (l): pair (Ah,Bl)
            {
                const u32 tb = stBase + (u32)5 * TILE_B;
                #pragma unroll
                for (int p = 0; p < 4; p++) {
                    u32 t4[4];
                    int row = bRowB + (p << 4);
                    ldmx4(t4, tb + swz(row, segB));
                    bf[2*p][0] = t4[0]; bf[2*p][1] = t4[1];
                    bf[2*p+1][0] = t4[2]; bf[2*p+1][1] = t4[3];
                }
                #pragma unroll
                for (int mt = 0; mt < 2; mt++)
                    #pragma unroll
                    for (int nt = 0; nt < 8; nt++)
                        mma16816(acc[mt][nt], af[0][mt], bf[nt]);
            }
        }
        __syncthreads();
    }

    // ---- epilogue ----
    const int qr = lane >> 2;
    const int qc = (lane & 3) << 1;
    #pragma unroll
    for (int mt = 0; mt < 2; mt++) {
        #pragma unroll
        for (int half = 0; half < 2; half++) {
            const int r = rowBase + (warpM << 5) + (mt << 4) + (half << 3) + qr;
            #pragma unroll
            for (int nt = 0; nt < 8; nt++) {
                const int cc = colBase + (warpN << 6) + (nt << 3) + qc;
                float v0 = acc[mt][nt][2*half + 0];
                float v1 = acc[mt][nt][2*half + 1];
                if (bias) { v0 += __ldg(&bias[cc]); v1 += __ldg(&bias[cc + 1]); }
                if (epi == 1) {
                    v0 = 0.5f * v0 * (1.0f + erff(v0 * 0.7071067811865475f));
                    v1 = 0.5f * v1 * (1.0f + erff(v1 * 0.7071067811865475f));
                }
                if (resid) {
                    v0 += resid[(size_t)r * ldc + cc];
                    v1 += resid[(size_t)r * ldc + cc + 1];
                }
                *(float2*)(C + (size_t)r * ldc + cc) = make_float2(v0, v1);
            }
        }
    }
}

// ---------------- router self-attention (8 pos, 12 heads, hd=64) ----------------
__global__ void __launch_bounds__(96) router_attn_kernel(
    const float* __restrict__ QKV, float* __restrict__ O)
{
    __shared__ float sK[8 * 768];
    __shared__ float sV[8 * 768];
    const int t = blockIdx.x, tid = threadIdx.x;
    const float* base = QKV + (size_t)t * 8 * 2304;
    for (int i = tid; i < 8 * 768; i += 96) {
        int pos = i / 768, c = i - pos * 768;
        sK[i] = base[(size_t)pos * 2304 +  768 + c];
        sV[i] = base[(size_t)pos * 2304 + 1536 + c];
    }
    __syncthreads();
    const int head = tid / 8, qi = tid % 8;
    const float* q = base + (size_t)qi * 2304 + head * 64;
    float s[8] = {0.f};
    for (int d = 0; d < 64; d++) {
        float qd = q[d];
        #pragma unroll
        for (int m = 0; m < 8; m++) s[m] = fmaf(qd, sK[m * 768 + head * 64 + d], s[m]);
    }
    float mx = -1e30f;
    #pragma unroll
    for (int m = 0; m < 8; m++) { s[m] *= 0.125f; mx = fmaxf(mx, s[m]); }
    float den = 0.f;
    #pragma unroll
    for (int m = 0; m < 8; m++) { s[m] = expf(s[m] - mx); den += s[m]; }
    float inv = 1.0f / den;
    #pragma unroll
    for (int m = 0; m < 8; m++) s[m] *= inv;
    float* op = O + (size_t)(t * 8 + qi) * 768 + head * 64;
    for (int d = 0; d < 64; d++) {
        float o = 0.f;
        #pragma unroll
        for (int m = 0; m < 8; m++) o = fmaf(s[m], sV[m * 768 + head * 64 + d], o);
        op[d] = o;
    }
}

__global__ void __launch_bounds__(256) rms_kernel(
    const float* __restrict__ Y, const float* __restrict__ R,
    const float* __restrict__ W, float* __restrict__ O)
{
    const int row = blockIdx.x, tid = threadIdx.x;
    const float* y = Y + (size_t)row * 768;
    const float* r = R + (size_t)row * 768;
    float v[3]; float ss = 0.f;
    #pragma unroll
    for (int i = 0; i < 3; i++) {
        int c = tid + i * 256;
        float s = y[c] + r[c];
        v[i] = s; ss = fmaf(s, s, ss);
    }
    __shared__ float red[256];
    red[tid] = ss; __syncthreads();
    for (int o = 128; o > 0; o >>= 1) { if (tid < o) red[tid] += red[tid + o]; __syncthreads(); }
    float scale = rsqrtf(red[0] * (1.0f / 768.0f) + 1e-5f);
    #pragma unroll
    for (int i = 0; i < 3; i++) {
        int c = tid + i * 256;
        O[(size_t)row * 768 + c] = v[i] * scale * W[c];
    }
}

__global__ void __launch_bounds__(256) logits_kernel(
    const float* __restrict__ CTX, const float* __restrict__ GW,
    float* __restrict__ rprobs, int* __restrict__ tkidx,
    float* __restrict__ tkp, float* __restrict__ out_idx_f)
{
    const int t = blockIdx.x, tid = threadIdx.x;
    __shared__ float mv[768];
    const float* c0 = CTX + (size_t)t * 8 * 768;
    for (int i = tid; i < 768; i += 256) {
        float s = 0.f;
        #pragma unroll
        for (int p = 0; p < 8; p++) s += c0[p * 768 + i];
        mv[i] = s * 0.125f;
    }
    __syncthreads();
    const int w = tid >> 5, lane = tid & 31;
    float part = 0.f;
    for (int i = lane; i < 768; i += 32) part = fmaf(mv[i], GW[w * 768 + i], part);
    #pragma unroll
    for (int o = 16; o; o >>= 1) part += __shfl_xor_sync(0xffffffffu, part, o);
    __shared__ float lg[8];
    if (lane == 0) lg[w] = part;
    __syncthreads();
    if (tid == 0) {
        float mx = lg[0];
        #pragma unroll
        for (int e = 1; e < 8; e++) mx = fmaxf(mx, lg[e]);
        float ex[8], den = 0.f;
        #pragma unroll
        for (int e = 0; e < 8; e++) { ex[e] = expf(lg[e] - mx); den += ex[e]; }
        float inv = 1.0f / den;
        #pragma unroll
        for (int e = 0; e < 8; e++) rprobs[t * 8 + e] = ex[e] * inv;
        int i0 = 0;
        #pragma unroll
        for (int e = 1; e < 8; e++) if (lg[e] > lg[i0]) i0 = e;
        int i1 = -1;
        #pragma unroll
        for (int e = 0; e < 8; e++) if (e != i0 && (i1 < 0 || lg[e] > lg[i1])) i1 = e;
        tkidx[t * 2] = i0; tkidx[t * 2 + 1] = i1;
        float eb = expf(lg[i1] - lg[i0]);
        float p0 = 1.0f / (1.0f + eb);
        tkp[t * 2] = p0; tkp[t * 2 + 1] = eb * p0;
        if (out_idx_f) { out_idx_f[t * 2] = (float)i0; out_idx_f[t * 2 + 1] = (float)i1; }
    }
}

__global__ void gather_kernel(const float* __restrict__ eo, const int* __restrict__ tkidx,
                              float* __restrict__ sf)
{
    const int total = TT * KX * DD;
    for (int idx = blockIdx.x * blockDim.x + threadIdx.x; idx < total; idx += gridDim.x * blockDim.x) {
        int d = idx % DD;
        int r = idx / DD;
        int t = r >> 1, k = r & 1;
        sf[idx] = eo[(size_t)t * EE * DD + (size_t)tkidx[t * 2 + k] * DD + d];
    }
}

__global__ void __launch_bounds__(256) collab_attn_kernel(
    const float* __restrict__ QKV, float* __restrict__ O, float* __restrict__ ent)
{
    const int t = blockIdx.x, tid = threadIdx.x;
    const float* base = QKV + (size_t)t * 2 * 2304;
    __shared__ float sc[2][2][2];
    __shared__ float sp[2][2][2];
    const int w = tid >> 5, lane = tid & 31;
    {
        int h = (w >> 2) & 1, qi = (w >> 1) & 1, kj = w & 1;
        float part = 0.f;
        const float* qp = base + (size_t)qi * 2304 + h * 384;
        const float* kp = base + (size_t)kj * 2304 + 768 + h * 384;
        for (int d = lane; d < 384; d += 32) part = fmaf(qp[d], kp[d], part);
        #pragma unroll
        for (int o = 16; o; o >>= 1) part += __shfl_xor_sync(0xffffffffu, part, o);
        if (lane == 0) sc[h][qi][kj] = part * 0.05103103630798288f;
    }
    __syncthreads();
    if (tid < 4) {
        int h = tid >> 1, qi = tid & 1;
        float s0 = sc[h][qi][0], s1 = sc[h][qi][1];
        float m = fmaxf(s0, s1);
        float e0 = expf(s0 - m), e1 = expf(s1 - m);
        float inv = 1.0f / (e0 + e1);
        sp[h][qi][0] = e0 * inv; sp[h][qi][1] = e1 * inv;
    }
    __syncthreads();
    if (tid == 0) {
        float esum = 0.f;
        #pragma unroll
        for (int qi = 0; qi < 2; qi++) {
            float a0 = 0.5f * (sp[0][qi][0] + sp[1][qi][0]);
            float a1 = 0.5f * (sp[0][qi][1] + sp[1][qi][1]);
            esum -= a0 * logf(a0 + 1e-9f) + a1 * logf(a1 + 1e-9f);
        }
        ent[t] = esum;
    }
    for (int i = tid; i < 2 * 768; i += 256) {
        int qi = i / 768, c = i - qi * 768;
        int h = c / 384;
        float p0 = sp[h][qi][0], p1 = sp[h][qi][1];
        O[(size_t)(t * 2 + qi) * 768 + c] = fmaf(p0, base[1536 + c], p1 * base[2304 + 1536 + c]);
    }
}

__global__ void combine_kernel(const float* __restrict__ ref, const float* __restrict__ tkp,
                               float* __restrict__ comb)
{
    const int total = TT * DD;
    for (int idx = blockIdx.x * blockDim.x + threadIdx.x; idx < total; idx += gridDim.x * blockDim.x) {
        int t = idx / DD, d = idx - t * DD;
        comb[idx] = fmaf(tkp[t * 2], ref[(size_t)(t * 2) * DD + d],
                         tkp[t * 2 + 1] * ref[(size_t)(t * 2 + 1) * DD + d]);
    }
}

__global__ void __launch_bounds__(256) aux_kernel(
    const float* __restrict__ rprobs, const float* __restrict__ ent, float* __restrict__ outp)
{
    const int tid = threadIdx.x;
    __shared__ float red[256];
    float us[8] = {0.f};
    for (int t = tid; t < TT; t += 256)
        #pragma unroll
        for (int e = 0; e < 8; e++) us[e] += rprobs[t * 8 + e];
    float usage[8];
    for (int e = 0; e < 8; e++) {
        red[tid] = us[e]; __syncthreads();
        for (int o = 128; o > 0; o >>= 1) { if (tid < o) red[tid] += red[tid + o]; __syncthreads(); }
        usage[e] = red[0] / (float)TT; __syncthreads();
    }
    float es = 0.f;
    for (int t = tid; t < TT; t += 256) es += ent[t];
    red[tid] = es; __syncthreads();
    for (int o = 128; o > 0; o >>= 1) { if (tid < o) red[tid] += red[tid + o]; __syncthreads(); }
    if (tid == 0) {
        float um = 0.f;
        #pragma unroll
        for (int e = 0; e < 8; e++) um += usage[e];
        um *= 0.125f;
        float bal = 0.f;
        #pragma unroll
        for (int e = 0; e < 8; e++) { float d = usage[e] - um; bal = fmaf(d, d, bal); }
        bal *= 0.125f;
        outp[0] = 0.1f * (0.01f * (red[0] / (float)(TT * KX)) + 0.01f * bal);
    }
}

// ---------------- host launch ----------------
extern "C" void kernel_launch(void* const* d_in, const int* in_sizes, int n_in,
                              void* d_out, int out_size)
{
    const float* x       = (const float*)d_in[0];
    const float* w1      = (const float*)d_in[1];
    const float* w3      = (const float*)d_in[2];
    const float* w2      = (const float*)d_in[3];
    const float* r_in_w  = (const float*)d_in[4];
    const float* r_in_b  = (const float*)d_in[5];
    const float* r_out_w = (const float*)d_in[6];
    const float* r_out_b = (const float*)d_in[7];
    const float* r_norm  = (const float*)d_in[8];
    const float* gate_w  = (const float*)d_in[9];
    const float* c_in_w  = (const float*)d_in[10];
    const float* c_in_b  = (const float*)d_in[11];
    const float* c_out_w = (const float*)d_in[12];
    const float* c_out_b = (const float*)d_in[13];
    const float* c_norm  = (const float*)d_in[14];
    const float* ffn_w1  = (const float*)d_in[15];
    const float* ffn_w2  = (const float*)d_in[16];
    const float* o_w     = (const float*)d_in[17];
    float* out = (float*)d_out;

    static bool attr_done = false;
    if (!attr_done) {
        cudaFuncSetAttribute(tgemm, cudaFuncAttributeMaxDynamicSharedMemorySize, TG_SMEM);
        attr_done = true;
    }

    float *gatep, *upp, *eo, *qkv, *attn, *proj, *ctx, *rprobs, *tkp, *sf, *ao, *h1, *ref, *comb, *ent;
    int* tkidx;
    bf16 *xS, *w1T, *w3T, *w2T, *actS, *eoS, *gS, *rinS, *routS, *cinS, *coutS, *f1S, *f2S, *owS;
    cudaGetSymbolAddress((void**)&gatep, g_gate);
    cudaGetSymbolAddress((void**)&upp,   g_up);
    cudaGetSymbolAddress((void**)&eo,    g_eo);
    cudaGetSymbolAddress((void**)&qkv,   g_qkv);
    cudaGetSymbolAddress((void**)&attn,  g_attn);
    cudaGetSymbolAddress((void**)&proj,  g_proj);
    cudaGetSymbolAddress((void**)&ctx,   g_ctx);
    cudaGetSymbolAddress((void**)&rprobs,g_rprobs);
    cudaGetSymbolAddress((void**)&tkidx, g_tkidx);
    cudaGetSymbolAddress((void**)&tkp,   g_tkp);
    cudaGetSymbolAddress((void**)&sf,    g_sf);
    cudaGetSymbolAddress((void**)&ao,    g_ao);
    cudaGetSymbolAddress((void**)&h1,    g_h1);
    cudaGetSymbolAddress((void**)&ref,   g_ref);
    cudaGetSymbolAddress((void**)&comb,  g_comb);
    cudaGetSymbolAddress((void**)&ent,   g_ent);
    cudaGetSymbolAddress((void**)&xS,    g_xS);
    cudaGetSymbolAddress((void**)&w1T,   g_w1T);
    cudaGetSymbolAddress((void**)&w3T,   g_w3T);
    cudaGetSymbolAddress((void**)&w2T,   g_w2T);
    cudaGetSymbolAddress((void**)&actS,  g_actS);
    cudaGetSymbolAddress((void**)&eoS,   g_eoS);
    cudaGetSymbolAddress((void**)&gS,    g_gS);
    cudaGetSymbolAddress((void**)&rinS,  g_rinS);
    cudaGetSymbolAddress((void**)&routS, g_routS);
    cudaGetSymbolAddress((void**)&cinS,  g_cinS);
    cudaGetSymbolAddress((void**)&coutS, g_coutS);
    cudaGetSymbolAddress((void**)&f1S,   g_f1S);
    cudaGetSymbolAddress((void**)&f2S,   g_f2S);
    cudaGetSymbolAddress((void**)&owS,   g_owS);

    const bool write_idx = out_size >= (TT * DD + 1 + TT * KX);
    const bool write_aux = out_size >= (TT * DD + 1);
    const size_t sEHD = (size_t)EE * HH * DD;
    const size_t sETH = (size_t)EE * TT * HH;
    const size_t sBig = (size_t)TT * EE * DD;
    const size_t sMid = (size_t)TT * KX * DD;
    const size_t sSm  = (size_t)TT * DD;
    dim3 tb32(32, 8);

    // launches 0-4 (so ncu -s 5 profiles the gate tgemm)
    split3<<<1024, 256>>>(x, xS, sSm, sSm);                          // 0
    tsplit<<<dim3(HH/32, DD/32, EE), tb32>>>(w1, w1T, DD, HH, sEHD); // 1
    tsplit<<<dim3(HH/32, DD/32, EE), tb32>>>(w3, w3T, DD, HH, sEHD); // 2
    tsplit<<<dim3(DD/32, HH/32, EE), tb32>>>(w2, w2T, HH, DD, (size_t)EE * DD * HH); // 3
    split3<<<512, 256>>>(r_in_w, rinS, (size_t)3*DD*DD, (size_t)3*DD*DD);            // 4

    // 5: gate GEMM (profiled)
    tgemm<<<dim3(HH/128, TT/128, EE), 256, TG_SMEM>>>(
        xS, sSm, 0, w1T, sEHD, (size_t)HH*DD, DD,
        nullptr, nullptr, gatep, HH, (size_t)TT*HH, 0);
    // 6: up GEMM
    tgemm<<<dim3(HH/128, TT/128, EE), 256, TG_SMEM>>>(
        xS, sSm, 0, w3T, sEHD, (size_t)HH*DD, DD,
        nullptr, nullptr, upp, HH, (size_t)TT*HH, 0);
    // remaining weight splits
    split3<<<512, 256>>>(r_out_w, routS, (size_t)DD*DD, (size_t)DD*DD);
    split3<<<512, 256>>>(c_in_w, cinS, (size_t)3*DD*DD, (size_t)3*DD*DD);
    split3<<<512, 256>>>(c_out_w, coutS, (size_t)DD*DD, (size_t)DD*DD);
    split3<<<512, 256>>>(ffn_w1, f1S, (size_t)DD*DD, (size_t)DD*DD);
    split3<<<512, 256>>>(ffn_w2, f2S, (size_t)DD*DD, (size_t)DD*DD);
    split3<<<512, 256>>>(o_w, owS, (size_t)DD*DD, (size_t)DD*DD);

    // act = silu(gate)*up -> splits
    split3_swiglu<<<8192, 256>>>(gatep, upp, actS, sETH, sETH);
    // expert down-proj
    tgemm<<<dim3(DD/128, TT/128, EE), 256, TG_SMEM>>>(
        actS, sETH, (size_t)TT*HH, w2T, (size_t)EE*DD*HH, (size_t)DD*HH, HH,
        nullptr, nullptr, eo, EE*DD, (size_t)DD, 0);
    // router qkv
    split3<<<4096, 256>>>(eo, eoS, sBig, sBig);
    tgemm<<<dim3(3*DD/128, TT*EE/128, 1), 256, TG_SMEM>>>(
        eoS, sBig, 0, rinS, (size_t)3*DD*DD, 0, DD,
        r_in_b, nullptr, qkv, 3*DD, 0, 0);
    // router attention
    router_attn_kernel<<<TT, 96>>>(qkv, attn);
    // router out-proj
    split3<<<4096, 256>>>(attn, gS, sBig, sBig);
    tgemm<<<dim3(DD/128, TT*EE/128, 1), 256, TG_SMEM>>>(
        gS, sBig, 0, routS, (size_t)DD*DD, 0, DD,
        r_out_b, nullptr, proj, DD, 0, 0);
    // residual + RMS
    rms_kernel<<<TT * EE, 256>>>(proj, eo, r_norm, ctx);
    // logits / top-2
    logits_kernel<<<TT, 256>>>(ctx, gate_w, rprobs, tkidx, tkp,
                               write_idx ? out + sSm + 1 : nullptr);
    // gather
    gather_kernel<<<4096, 256>>>(eo, tkidx, sf);
    // collab qkv
    split3<<<2048, 256>>>(sf, gS, sMid, sMid);
    tgemm<<<dim3(3*DD/128, TT*KX/128, 1), 256, TG_SMEM>>>(
        gS, sMid, 0, cinS, (size_t)3*DD*DD, 0, DD,
        c_in_b, nullptr, qkv, 3*DD, 0, 0);
    // collab attention + entropy
    collab_attn_kernel<<<TT, 256>>>(qkv, attn, ent);
    // collab out-proj
    split3<<<2048, 256>>>(attn, gS, sMid, sMid);
    tgemm<<<dim3(DD/128, TT*KX/128, 1), 256, TG_SMEM>>>(
        gS, sMid, 0, coutS, (size_t)DD*DD, 0, DD,
        c_out_b, nullptr, proj, DD, 0, 0);
    // residual + RMS
    rms_kernel<<<TT * KX, 256>>>(proj, sf, c_norm, ao);
    // FFN up + GELU
    split3<<<2048, 256>>>(ao, gS, sMid, sMid);
    tgemm<<<dim3(DD/128, TT*KX/128, 1), 256, TG_SMEM>>>(
        gS, sMid, 0, f1S, (size_t)DD*DD, 0, DD,
        nullptr, nullptr, h1, DD, 0, 1);
    // FFN down + residual(ao)
    split3<<<2048, 256>>>(h1, gS, sMid, sMid);
    tgemm<<<dim3(DD/128, TT*KX/128, 1), 256, TG_SMEM>>>(
        gS, sMid, 0, f2S, (size_t)DD*DD, 0, DD,
        nullptr, ao, ref, DD, 0, 0);
    // combine
    combine_kernel<<<2048, 256>>>(ref, tkp, comb);
    // output projection
    split3<<<1024, 256>>>(comb, gS, sSm, sSm);
    tgemm<<<dim3(DD/128, TT/128, 1), 256, TG_SMEM>>>(
        gS, sSm, 0, owS, (size_t)DD*DD, 0, DD,
        nullptr, nullptr, out, DD, 0, 0);
    // aux
    if (write_aux)
        aux_kernel<<<1, 256>>>(rprobs, ent, out + sSm);
}

// round 9
// speedup vs baseline: 2.1280x; 2.1280x over previous
#include <cuda_runtime.h>
#include <cuda_bf16.h>
#include <math.h>
#include <stdint.h>

#define TT 4096
#define DD 768
#define EE 8
#define KX 2
#define HH 2048

typedef __nv_bfloat16 bf16;
typedef unsigned long long u64;
typedef unsigned int u32;

// ---------------- fp32 scratch ----------------
__device__ __align__(16) float g_gate[(size_t)EE*TT*HH];
__device__ __align__(16) float g_up  [(size_t)EE*TT*HH];
__device__ __align__(16) float g_eo  [(size_t)TT*EE*DD];
__device__ __align__(16) float g_qkv [(size_t)TT*EE*3*DD];
__device__ __align__(16) float g_attn[(size_t)TT*EE*DD];
__device__ __align__(16) float g_proj[(size_t)TT*EE*DD];
__device__ __align__(16) float g_ctx [(size_t)TT*EE*DD];
__device__ float g_rprobs[TT*EE];
__device__ int   g_tkidx[TT*KX];
__device__ float g_tkp  [TT*KX];
__device__ __align__(16) float g_sf [(size_t)TT*KX*DD];
__device__ __align__(16) float g_ao [(size_t)TT*KX*DD];
__device__ __align__(16) float g_h1 [(size_t)TT*KX*DD];
__device__ __align__(16) float g_ref[(size_t)TT*KX*DD];
__device__ __align__(16) float g_comb[(size_t)TT*DD];
__device__ float g_ent[TT];

// ---------------- bf16 split buffers (2 planes used) ----------------
__device__ __align__(16) bf16 g_xS   [2*(size_t)TT*DD];
__device__ __align__(16) bf16 g_w1T  [2*(size_t)EE*HH*DD];
__device__ __align__(16) bf16 g_w3T  [2*(size_t)EE*HH*DD];
__device__ __align__(16) bf16 g_w2T  [2*(size_t)EE*DD*HH];
__device__ __align__(16) bf16 g_actS [2*(size_t)EE*TT*HH];
__device__ __align__(16) bf16 g_eoS  [2*(size_t)TT*EE*DD];
__device__ __align__(16) bf16 g_gS   [2*(size_t)TT*EE*DD];
__device__ __align__(16) bf16 g_rinS [2*(size_t)3*DD*DD];
__device__ __align__(16) bf16 g_routS[2*(size_t)DD*DD];
__device__ __align__(16) bf16 g_cinS [2*(size_t)3*DD*DD];
__device__ __align__(16) bf16 g_coutS[2*(size_t)DD*DD];
__device__ __align__(16) bf16 g_f1S  [2*(size_t)DD*DD];
__device__ __align__(16) bf16 g_f2S  [2*(size_t)DD*DD];
__device__ __align__(16) bf16 g_owS  [2*(size_t)DD*DD];

// ---------------- PTX helpers (sm_80+ only) ----------------
__device__ __forceinline__ u32 s2u(const void* p) {
    u32 a; asm("{ .reg .u64 t; cvta.to.shared.u64 t, %1; cvt.u32.u64 %0, t; }" : "=r"(a) : "l"(p));
    return a;
}
__device__ __forceinline__ void cpasync16(u32 saddr, const void* gaddr) {
    asm volatile("cp.async.cg.shared.global [%0], [%1], 16;" :: "r"(saddr), "l"(gaddr));
}
#define CP_COMMIT() asm volatile("cp.async.commit_group;" ::: "memory")
#define CP_WAIT(n)  asm volatile("cp.async.wait_group %0;" :: "n"(n) : "memory")

__device__ __forceinline__ void ldmx4(u32* r, u32 addr) {
    asm volatile("ldmatrix.sync.aligned.m8n8.x4.shared.b16 {%0,%1,%2,%3}, [%4];"
        : "=r"(r[0]), "=r"(r[1]), "=r"(r[2]), "=r"(r[3]) : "r"(addr));
}
__device__ __forceinline__ void mma16816(float* d, const u32* a, const u32* b) {
    asm volatile("mma.sync.aligned.m16n8k16.row.col.f32.bf16.bf16.f32 "
        "{%0,%1,%2,%3}, {%4,%5,%6,%7}, {%8,%9}, {%0,%1,%2,%3};"
        : "+f"(d[0]), "+f"(d[1]), "+f"(d[2]), "+f"(d[3])
        : "r"(a[0]), "r"(a[1]), "r"(a[2]), "r"(a[3]), "r"(b[0]), "r"(b[1]));
}

// ---------------- exact 2-way bf16 split ----------------
__device__ __forceinline__ void split2(float x, bf16& h, bf16& m) {
    h = __float2bfloat16(x);
    m = __float2bfloat16(x - __bfloat162float(h));
}
__global__ void split3(const float* __restrict__ in, bf16* __restrict__ out,
                       size_t ss, size_t n) {
    for (size_t i = (size_t)blockIdx.x*blockDim.x + threadIdx.x; i < n;
         i += (size_t)gridDim.x*blockDim.x) {
        bf16 h, m; split2(in[i], h, m);
        out[i] = h; out[ss + i] = m;
    }
}
__global__ void split3_swiglu(const float* __restrict__ g, const float* __restrict__ u,
                              bf16* __restrict__ out, size_t ss, size_t n) {
    for (size_t i = (size_t)blockIdx.x*blockDim.x + threadIdx.x; i < n;
         i += (size_t)gridDim.x*blockDim.x) {
        float gv = g[i];
        float x = gv / (1.0f + expf(-gv)) * u[i];
        bf16 h, m; split2(x, h, m);
        out[i] = h; out[ss + i] = m;
    }
}
// transpose+split: (z): Kd x Nd fp32 -> (z): Nd x Kd bf16 x2 (split stride ss)
__global__ void tsplit(const float* __restrict__ in, bf16* __restrict__ out,
                       int Kd, int Nd, size_t ss) {
    __shared__ float t[32][33];
    const float* ip = in + (size_t)blockIdx.z * Kd * Nd;
    bf16* op = out + (size_t)blockIdx.z * Kd * Nd;
    int n0 = blockIdx.x * 32, k0 = blockIdx.y * 32;
    int tx = threadIdx.x, ty0 = threadIdx.y;
    for (int ty = ty0; ty < 32; ty += 8)
        t[ty][tx] = ip[(size_t)(k0 + ty) * Nd + n0 + tx];
    __syncthreads();
    for (int ty = ty0; ty < 32; ty += 8) {
        bf16 h, m; split2(t[tx][ty], h, m);
        size_t o = (size_t)(n0 + ty) * Kd + k0 + tx;
        op[o] = h; op[ss + o] = m;
    }
}

// ---------------- mma.sync 2-split fp32 GEMM ----------------
// D = Ah@Bh^T + Am@Bh^T + Ah@Bm^T. grid (N/128, M/128, Z), 256 threads.
// K-chunk 64, smem row stride 144B (16-aligned), 4 tiles/stage.
#define TILE_B   18432              // 128*144
#define STAGE_B  (4*TILE_B)         // 73728
#define TG_SMEM  (2*STAGE_B)        // 147456

__global__ void __launch_bounds__(256, 1) tgemm(
    const bf16* __restrict__ A, size_t aSS, size_t sA,
    const bf16* __restrict__ B, size_t bSS, size_t sB,
    int Kd,
    const float* __restrict__ bias, const float* __restrict__ resid,
    float* __restrict__ C, int ldc, size_t sC, int epi)   // epi: 0 none, 1 GELU
{
    extern __shared__ __align__(16) char smc[];
    const int tid = threadIdx.x, wid = tid >> 5, lane = tid & 31;
    const u32 sb = s2u(smc);
    const int rowBase = blockIdx.y << 7;
    const int colBase = blockIdx.x << 7;
    const bf16* Az = A + (size_t)blockIdx.z * sA;
    const bf16* Bz = B + (size_t)blockIdx.z * sB;
    C += (size_t)blockIdx.z * sC;

    const int warpM = wid >> 1;
    const int warpN = wid & 1;

    // ---- async chunk loader: 4096 x 16B per chunk (K-chunk 64, 4 tiles) ----
    auto loadChunk = [&](int c, int st) {
        const int k0 = c << 6;
        const u32 stBase = sb + (u32)st * STAGE_B;
        #pragma unroll
        for (int it = 0; it < 16; it++) {
            int idx = tid + (it << 8);            // 0..4095
            int mat   = idx >> 11;                // 0=A 1=B
            int split = (idx >> 10) & 1;          // 0=h 1=m
            int rc    = idx & 1023;
            int row   = rc >> 3;                  // 0..127
            int seg   = rc & 7;                   // 8 bf16 each
            const bf16* src = (mat == 0)
                ? Az + (size_t)split * aSS + (size_t)(rowBase + row) * Kd + k0 + (seg << 3)
                : Bz + (size_t)split * bSS + (size_t)(colBase + row) * Kd + k0 + (seg << 3);
            u32 dst = stBase + (u32)((mat << 1) + split) * TILE_B + (u32)(row * 144 + (seg << 4));
            cpasync16(dst, src);
        }
    };

    float acc[2][8][4];
    #pragma unroll
    for (int mt = 0; mt < 2; mt++)
        #pragma unroll
        for (int nt = 0; nt < 8; nt++)
            #pragma unroll
            for (int j = 0; j < 4; j++) acc[mt][nt][j] = 0.f;

    const int nc = Kd >> 6;
    loadChunk(0, 0); CP_COMMIT();

    const int aRow = (warpM << 5) + (lane & 15);
    const u32 aColB = (u32)((lane >> 4) << 4);
    const int bRow = (warpN << 6) + ((lane >> 4) << 3) + (lane & 7);
    const u32 bColB = (u32)(((lane >> 3) & 1) << 4);

    for (int c = 0; c < nc; c++) {
        const int st = c & 1;
        if (c + 1 < nc) { loadChunk(c + 1, st ^ 1); CP_COMMIT(); CP_WAIT(1); }
        else CP_WAIT(0);
        __syncthreads();

        const u32 stBase = sb + (u32)st * STAGE_B;
        #pragma unroll
        for (int ks = 0; ks < 4; ks++) {
            const u32 kb = (u32)(ks << 5);   // 16 bf16 = 32B
            u32 af[2][2][4];
            #pragma unroll
            for (int s = 0; s < 2; s++) {
                const u32 abase = stBase + (u32)s * TILE_B + kb + aColB;
                #pragma unroll
                for (int mt = 0; mt < 2; mt++)
                    ldmx4(af[s][mt], abase + (u32)((aRow + (mt << 4)) * 144));
            }
            u32 bf[8][2];
            // B split h: pairs (Ah,Bh), (Am,Bh)
            {
                const u32 bbase = stBase + (u32)2 * TILE_B + kb + bColB;
                #pragma unroll
                for (int p = 0; p < 4; p++) {
                    u32 t4[4];
                    ldmx4(t4, bbase + (u32)((bRow + (p << 4)) * 144));
                    bf[2*p][0] = t4[0]; bf[2*p][1] = t4[1];
                    bf[2*p+1][0] = t4[2]; bf[2*p+1][1] = t4[3];
                }
                #pragma unroll
                for (int s = 0; s < 2; s++)
                    #pragma unroll
                    for (int mt = 0; mt < 2; mt++)
                        #pragma unroll
                        for (int nt = 0; nt < 8; nt++)
                            mma16816(acc[mt][nt], af[s][mt], bf[nt]);
            }
            // B split m: pair (Ah,Bm)
            {
                const u32 bbase = stBase + (u32)3 * TILE_B + kb + bColB;
                #pragma unroll
                for (int p = 0; p < 4; p++) {
                    u32 t4[4];
                    ldmx4(t4, bbase + (u32)((bRow + (p << 4)) * 144));
                    bf[2*p][0] = t4[0]; bf[2*p][1] = t4[1];
                    bf[2*p+1][0] = t4[2]; bf[2*p+1][1] = t4[3];
                }
                #pragma unroll
                for (int mt = 0; mt < 2; mt++)
                    #pragma unroll
                    for (int nt = 0; nt < 8; nt++)
                        mma16816(acc[mt][nt], af[0][mt], bf[nt]);
            }
        }
        __syncthreads();
    }

    // ---- epilogue ----
    const int qr = lane >> 2;
    const int qc = (lane & 3) << 1;
    #pragma unroll
    for (int mt = 0; mt < 2; mt++) {
        #pragma unroll
        for (int half = 0; half < 2; half++) {
            const int r = rowBase + (warpM << 5) + (mt << 4) + (half << 3) + qr;
            #pragma unroll
            for (int nt = 0; nt < 8; nt++) {
                const int cc = colBase + (warpN << 6) + (nt << 3) + qc;
                float v0 = acc[mt][nt][2*half + 0];
                float v1 = acc[mt][nt][2*half + 1];
                if (bias) { v0 += __ldg(&bias[cc]); v1 += __ldg(&bias[cc + 1]); }
                if (epi == 1) {
                    v0 = 0.5f * v0 * (1.0f + erff(v0 * 0.7071067811865475f));
                    v1 = 0.5f * v1 * (1.0f + erff(v1 * 0.7071067811865475f));
                }
                if (resid) {
                    v0 += resid[(size_t)r * ldc + cc];
                    v1 += resid[(size_t)r * ldc + cc + 1];
                }
                *(float2*)(C + (size_t)r * ldc + cc) = make_float2(v0, v1);
            }
        }
    }
}

// ---------------- router self-attention (8 pos, 12 heads, hd=64) ----------------
__global__ void __launch_bounds__(96) router_attn_kernel(
    const float* __restrict__ QKV, float* __restrict__ O)
{
    __shared__ float sK[8 * 768];
    __shared__ float sV[8 * 768];
    const int t = blockIdx.x, tid = threadIdx.x;
    const float* base = QKV + (size_t)t * 8 * 2304;
    for (int i = tid; i < 8 * 768; i += 96) {
        int pos = i / 768, c = i - pos * 768;
        sK[i] = base[(size_t)pos * 2304 +  768 + c];
        sV[i] = base[(size_t)pos * 2304 + 1536 + c];
    }
    __syncthreads();
    const int head = tid / 8, qi = tid % 8;
    const float* q = base + (size_t)qi * 2304 + head * 64;
    float s[8] = {0.f};
    for (int d = 0; d < 64; d++) {
        float qd = q[d];
        #pragma unroll
        for (int m = 0; m < 8; m++) s[m] = fmaf(qd, sK[m * 768 + head * 64 + d], s[m]);
    }
    float mx = -1e30f;
    #pragma unroll
    for (int m = 0; m < 8; m++) { s[m] *= 0.125f; mx = fmaxf(mx, s[m]); }
    float den = 0.f;
    #pragma unroll
    for (int m = 0; m < 8; m++) { s[m] = expf(s[m] - mx); den += s[m]; }
    float inv = 1.0f / den;
    #pragma unroll
    for (int m = 0; m < 8; m++) s[m] *= inv;
    float* op = O + (size_t)(t * 8 + qi) * 768 + head * 64;
    for (int d = 0; d < 64; d++) {
        float o = 0.f;
        #pragma unroll
        for (int m = 0; m < 8; m++) o = fmaf(s[m], sV[m * 768 + head * 64 + d], o);
        op[d] = o;
    }
}

__global__ void __launch_bounds__(256) rms_kernel(
    const float* __restrict__ Y, const float* __restrict__ R,
    const float* __restrict__ W, float* __restrict__ O)
{
    const int row = blockIdx.x, tid = threadIdx.x;
    const float* y = Y + (size_t)row * 768;
    const float* r = R + (size_t)row * 768;
    float v[3]; float ss = 0.f;
    #pragma unroll
    for (int i = 0; i < 3; i++) {
        int c = tid + i * 256;
        float s = y[c] + r[c];
        v[i] = s; ss = fmaf(s, s, ss);
    }
    __shared__ float red[256];
    red[tid] = ss; __syncthreads();
    for (int o = 128; o > 0; o >>= 1) { if (tid < o) red[tid] += red[tid + o]; __syncthreads(); }
    float scale = rsqrtf(red[0] * (1.0f / 768.0f) + 1e-5f);
    #pragma unroll
    for (int i = 0; i < 3; i++) {
        int c = tid + i * 256;
        O[(size_t)row * 768 + c] = v[i] * scale * W[c];
    }
}

__global__ void __launch_bounds__(256) logits_kernel(
    const float* __restrict__ CTX, const float* __restrict__ GW,
    float* __restrict__ rprobs, int* __restrict__ tkidx,
    float* __restrict__ tkp, float* __restrict__ out_idx_f)
{
    const int t = blockIdx.x, tid = threadIdx.x;
    __shared__ float mv[768];
    const float* c0 = CTX + (size_t)t * 8 * 768;
    for (int i = tid; i < 768; i += 256) {
        float s = 0.f;
        #pragma unroll
        for (int p = 0; p < 8; p++) s += c0[p * 768 + i];
        mv[i] = s * 0.125f;
    }
    __syncthreads();
    const int w = tid >> 5, lane = tid & 31;
    float part = 0.f;
    for (int i = lane; i < 768; i += 32) part = fmaf(mv[i], GW[w * 768 + i], part);
    #pragma unroll
    for (int o = 16; o; o >>= 1) part += __shfl_xor_sync(0xffffffffu, part, o);
    __shared__ float lg[8];
    if (lane == 0) lg[w] = part;
    __syncthreads();
    if (tid == 0) {
        float mx = lg[0];
        #pragma unroll
        for (int e = 1; e < 8; e++) mx = fmaxf(mx, lg[e]);
        float ex[8], den = 0.f;
        #pragma unroll
        for (int e = 0; e < 8; e++) { ex[e] = expf(lg[e] - mx); den += ex[e]; }
        float inv = 1.0f / den;
        #pragma unroll
        for (int e = 0; e < 8; e++) rprobs[t * 8 + e] = ex[e] * inv;
        int i0 = 0;
        #pragma unroll
        for (int e = 1; e < 8; e++) if (lg[e] > lg[i0]) i0 = e;
        int i1 = -1;
        #pragma unroll
        for (int e = 0; e < 8; e++) if (e != i0 && (i1 < 0 || lg[e] > lg[i1])) i1 = e;
        tkidx[t * 2] = i0; tkidx[t * 2 + 1] = i1;
        float eb = expf(lg[i1] - lg[i0]);
        float p0 = 1.0f / (1.0f + eb);
        tkp[t * 2] = p0; tkp[t * 2 + 1] = eb * p0;
        if (out_idx_f) { out_idx_f[t * 2] = (float)i0; out_idx_f[t * 2 + 1] = (float)i1; }
    }
}

__global__ void gather_kernel(const float* __restrict__ eo, const int* __restrict__ tkidx,
                              float* __restrict__ sf)
{
    const int total = TT * KX * DD;
    for (int idx = blockIdx.x * blockDim.x + threadIdx.x; idx < total; idx += gridDim.x * blockDim.x) {
        int d = idx % DD;
        int r = idx / DD;
        int t = r >> 1, k = r & 1;
        sf[idx] = eo[(size_t)t * EE * DD + (size_t)tkidx[t * 2 + k] * DD + d];
    }
}

__global__ void __launch_bounds__(256) collab_attn_kernel(
    const float* __restrict__ QKV, float* __restrict__ O, float* __restrict__ ent)
{
    const int t = blockIdx.x, tid = threadIdx.x;
    const float* base = QKV + (size_t)t * 2 * 2304;
    __shared__ float sc[2][2][2];
    __shared__ float sp[2][2][2];
    const int w = tid >> 5, lane = tid & 31;
    {
        int h = (w >> 2) & 1, qi = (w >> 1) & 1, kj = w & 1;
        float part = 0.f;
        const float* qp = base + (size_t)qi * 2304 + h * 384;
        const float* kp = base + (size_t)kj * 2304 + 768 + h * 384;
        for (int d = lane; d < 384; d += 32) part = fmaf(qp[d], kp[d], part);
        #pragma unroll
        for (int o = 16; o; o >>= 1) part += __shfl_xor_sync(0xffffffffu, part, o);
        if (lane == 0) sc[h][qi][kj] = part * 0.05103103630798288f;
    }
    __syncthreads();
    if (tid < 4) {
        int h = tid >> 1, qi = tid & 1;
        float s0 = sc[h][qi][0], s1 = sc[h][qi][1];
        float m = fmaxf(s0, s1);
        float e0 = expf(s0 - m), e1 = expf(s1 - m);
        float inv = 1.0f / (e0 + e1);
        sp[h][qi][0] = e0 * inv; sp[h][qi][1] = e1 * inv;
    }
    __syncthreads();
    if (tid == 0) {
        float esum = 0.f;
        #pragma unroll
        for (int qi = 0; qi < 2; qi++) {
            float a0 = 0.5f * (sp[0][qi][0] + sp[1][qi][0]);
            float a1 = 0.5f * (sp[0][qi][1] + sp[1][qi][1]);
            esum -= a0 * logf(a0 + 1e-9f) + a1 * logf(a1 + 1e-9f);
        }
        ent[t] = esum;
    }
    for (int i = tid; i < 2 * 768; i += 256) {
        int qi = i / 768, c = i - qi * 768;
        int h = c / 384;
        float p0 = sp[h][qi][0], p1 = sp[h][qi][1];
        O[(size_t)(t * 2 + qi) * 768 + c] = fmaf(p0, base[1536 + c], p1 * base[2304 + 1536 + c]);
    }
}

__global__ void combine_kernel(const float* __restrict__ ref, const float* __restrict__ tkp,
                               float* __restrict__ comb)
{
    const int total = TT * DD;
    for (int idx = blockIdx.x * blockDim.x + threadIdx.x; idx < total; idx += gridDim.x * blockDim.x) {
        int t = idx / DD, d = idx - t * DD;
        comb[idx] = fmaf(tkp[t * 2], ref[(size_t)(t * 2) * DD + d],
                         tkp[t * 2 + 1] * ref[(size_t)(t * 2 + 1) * DD + d]);
    }
}

__global__ void __launch_bounds__(256) aux_kernel(
    const float* __restrict__ rprobs, const float* __restrict__ ent, float* __restrict__ outp)
{
    const int tid = threadIdx.x;
    __shared__ float red[256];
    float us[8] = {0.f};
    for (int t = tid; t < TT; t += 256)
        #pragma unroll
        for (int e = 0; e < 8; e++) us[e] += rprobs[t * 8 + e];
    float usage[8];
    for (int e = 0; e < 8; e++) {
        red[tid] = us[e]; __syncthreads();
        for (int o = 128; o > 0; o >>= 1) { if (tid < o) red[tid] += red[tid + o]; __syncthreads(); }
        usage[e] = red[0] / (float)TT; __syncthreads();
    }
    float es = 0.f;
    for (int t = tid; t < TT; t += 256) es += ent[t];
    red[tid] = es; __syncthreads();
    for (int o = 128; o > 0; o >>= 1) { if (tid < o) red[tid] += red[tid + o]; __syncthreads(); }
    if (tid == 0) {
        float um = 0.f;
        #pragma unroll
        for (int e = 0; e < 8; e++) um += usage[e];
        um *= 0.125f;
        float bal = 0.f;
        #pragma unroll
        for (int e = 0; e < 8; e++) { float d = usage[e] - um; bal = fmaf(d, d, bal); }
        bal *= 0.125f;
        outp[0] = 0.1f * (0.01f * (red[0] / (float)(TT * KX)) + 0.01f * bal);
    }
}

// ---------------- host launch ----------------
extern "C" void kernel_launch(void* const* d_in, const int* in_sizes, int n_in,
                              void* d_out, int out_size)
{
    const float* x       = (const float*)d_in[0];
    const float* w1      = (const float*)d_in[1];
    const float* w3      = (const float*)d_in[2];
    const float* w2      = (const float*)d_in[3];
    const float* r_in_w  = (const float*)d_in[4];
    const float* r_in_b  = (const float*)d_in[5];
    const float* r_out_w = (const float*)d_in[6];
    const float* r_out_b = (const float*)d_in[7];
    const float* r_norm  = (const float*)d_in[8];
    const float* gate_w  = (const float*)d_in[9];
    const float* c_in_w  = (const float*)d_in[10];
    const float* c_in_b  = (const float*)d_in[11];
    const float* c_out_w = (const float*)d_in[12];
    const float* c_out_b = (const float*)d_in[13];
    const float* c_norm  = (const float*)d_in[14];
    const float* ffn_w1  = (const float*)d_in[15];
    const float* ffn_w2  = (const float*)d_in[16];
    const float* o_w     = (const float*)d_in[17];
    float* out = (float*)d_out;

    static bool attr_done = false;
    if (!attr_done) {
        cudaFuncSetAttribute(tgemm, cudaFuncAttributeMaxDynamicSharedMemorySize, TG_SMEM);
        attr_done = true;
    }

    float *gatep, *upp, *eo, *qkv, *attn, *proj, *ctx, *rprobs, *tkp, *sf, *ao, *h1, *ref, *comb, *ent;
    int* tkidx;
    bf16 *xS, *w1T, *w3T, *w2T, *actS, *eoS, *gS, *rinS, *routS, *cinS, *coutS, *f1S, *f2S, *owS;
    cudaGetSymbolAddress((void**)&gatep, g_gate);
    cudaGetSymbolAddress((void**)&upp,   g_up);
    cudaGetSymbolAddress((void**)&eo,    g_eo);
    cudaGetSymbolAddress((void**)&qkv,   g_qkv);
    cudaGetSymbolAddress((void**)&attn,  g_attn);
    cudaGetSymbolAddress((void**)&proj,  g_proj);
    cudaGetSymbolAddress((void**)&ctx,   g_ctx);
    cudaGetSymbolAddress((void**)&rprobs,g_rprobs);
    cudaGetSymbolAddress((void**)&tkidx, g_tkidx);
    cudaGetSymbolAddress((void**)&tkp,   g_tkp);
    cudaGetSymbolAddress((void**)&sf,    g_sf);
    cudaGetSymbolAddress((void**)&ao,    g_ao);
    cudaGetSymbolAddress((void**)&h1,    g_h1);
    cudaGetSymbolAddress((void**)&ref,   g_ref);
    cudaGetSymbolAddress((void**)&comb,  g_comb);
    cudaGetSymbolAddress((void**)&ent,   g_ent);
    cudaGetSymbolAddress((void**)&xS,    g_xS);
    cudaGetSymbolAddress((void**)&w1T,   g_w1T);
    cudaGetSymbolAddress((void**)&w3T,   g_w3T);
    cudaGetSymbolAddress((void**)&w2T,   g_w2T);
    cudaGetSymbolAddress((void**)&actS,  g_actS);
    cudaGetSymbolAddress((void**)&eoS,   g_eoS);
    cudaGetSymbolAddress((void**)&gS,    g_gS);
    cudaGetSymbolAddress((void**)&rinS,  g_rinS);
    cudaGetSymbolAddress((void**)&routS, g_routS);
    cudaGetSymbolAddress((void**)&cinS,  g_cinS);
    cudaGetSymbolAddress((void**)&coutS, g_coutS);
    cudaGetSymbolAddress((void**)&f1S,   g_f1S);
    cudaGetSymbolAddress((void**)&f2S,   g_f2S);
    cudaGetSymbolAddress((void**)&owS,   g_owS);

    const bool write_idx = out_size >= (TT * DD + 1 + TT * KX);
    const bool write_aux = out_size >= (TT * DD + 1);
    const size_t sEHD = (size_t)EE * HH * DD;
    const size_t sETH = (size_t)EE * TT * HH;
    const size_t sBig = (size_t)TT * EE * DD;
    const size_t sMid = (size_t)TT * KX * DD;
    const size_t sSm  = (size_t)TT * DD;
    dim3 tb32(32, 8);

    // launches 0-4 (so ncu -s 5 profiles the gate tgemm)
    split3<<<1024, 256>>>(x, xS, sSm, sSm);                          // 0
    tsplit<<<dim3(HH/32, DD/32, EE), tb32>>>(w1, w1T, DD, HH, sEHD); // 1
    tsplit<<<dim3(HH/32, DD/32, EE), tb32>>>(w3, w3T, DD, HH, sEHD); // 2
    tsplit<<<dim3(DD/32, HH/32, EE), tb32>>>(w2, w2T, HH, DD, (size_t)EE * DD * HH); // 3
    split3<<<512, 256>>>(r_in_w, rinS, (size_t)3*DD*DD, (size_t)3*DD*DD);            // 4

    // 5: gate GEMM (profiled)
    tgemm<<<dim3(HH/128, TT/128, EE), 256, TG_SMEM>>>(
        xS, sSm, 0, w1T, sEHD, (size_t)HH*DD, DD,
        nullptr, nullptr, gatep, HH, (size_t)TT*HH, 0);
    // 6: up GEMM
    tgemm<<<dim3(HH/128, TT/128, EE), 256, TG_SMEM>>>(
        xS, sSm, 0, w3T, sEHD, (size_t)HH*DD, DD,
        nullptr, nullptr, upp, HH, (size_t)TT*HH, 0);
    // remaining weight splits
    split3<<<512, 256>>>(r_out_w, routS, (size_t)DD*DD, (size_t)DD*DD);
    split3<<<512, 256>>>(c_in_w, cinS, (size_t)3*DD*DD, (size_t)3*DD*DD);
    split3<<<512, 256>>>(c_out_w, coutS, (size_t)DD*DD, (size_t)DD*DD);
    split3<<<512, 256>>>(ffn_w1, f1S, (size_t)DD*DD, (size_t)DD*DD);
    split3<<<512, 256>>>(ffn_w2, f2S, (size_t)DD*DD, (size_t)DD*DD);
    split3<<<512, 256>>>(o_w, owS, (size_t)DD*DD, (size_t)DD*DD);

    // act = silu(gate)*up -> splits
    split3_swiglu<<<8192, 256>>>(gatep, upp, actS, sETH, sETH);
    // expert down-proj
    tgemm<<<dim3(DD/128, TT/128, EE), 256, TG_SMEM>>>(
        actS, sETH, (size_t)TT*HH, w2T, (size_t)EE*DD*HH, (size_t)DD*HH, HH,
        nullptr, nullptr, eo, EE*DD, (size_t)DD, 0);
    // router qkv
    split3<<<4096, 256>>>(eo, eoS, sBig, sBig);
    tgemm<<<dim3(3*DD/128, TT*EE/128, 1), 256, TG_SMEM>>>(
        eoS, sBig, 0, rinS, (size_t)3*DD*DD, 0, DD,
        r_in_b, nullptr, qkv, 3*DD, 0, 0);
    // router attention
    router_attn_kernel<<<TT, 96>>>(qkv, attn);
    // router out-proj
    split3<<<4096, 256>>>(attn, gS, sBig, sBig);
    tgemm<<<dim3(DD/128, TT*EE/128, 1), 256, TG_SMEM>>>(
        gS, sBig, 0, routS, (size_t)DD*DD, 0, DD,
        r_out_b, nullptr, proj, DD, 0, 0);
    // residual + RMS
    rms_kernel<<<TT * EE, 256>>>(proj, eo, r_norm, ctx);
    // logits / top-2
    logits_kernel<<<TT, 256>>>(ctx, gate_w, rprobs, tkidx, tkp,
                               write_idx ? out + sSm + 1 : nullptr);
    // gather
    gather_kernel<<<4096, 256>>>(eo, tkidx, sf);
    // collab qkv
    split3<<<2048, 256>>>(sf, gS, sMid, sMid);
    tgemm<<<dim3(3*DD/128, TT*KX/128, 1), 256, TG_SMEM>>>(
        gS, sMid, 0, cinS, (size_t)3*DD*DD, 0, DD,
        c_in_b, nullptr, qkv, 3*DD, 0, 0);
    // collab attention + entropy
    collab_attn_kernel<<<TT, 256>>>(qkv, attn, ent);
    // collab out-proj
    split3<<<2048, 256>>>(attn, gS, sMid, sMid);
    tgemm<<<dim3(DD/128, TT*KX/128, 1), 256, TG_SMEM>>>(
        gS, sMid, 0, coutS, (size_t)DD*DD, 0, DD,
        c_out_b, nullptr, proj, DD, 0, 0);
    // residual + RMS
    rms_kernel<<<TT * KX, 256>>>(proj, sf, c_norm, ao);
    // FFN up + GELU
    split3<<<2048, 256>>>(ao, gS, sMid, sMid);
    tgemm<<<dim3(DD/128, TT*KX/128, 1), 256, TG_SMEM>>>(
        gS, sMid, 0, f1S, (size_t)DD*DD, 0, DD,
        nullptr, nullptr, h1, DD, 0, 1);
    // FFN down + residual(ao)
    split3<<<2048, 256>>>(h1, gS, sMid, sMid);
    tgemm<<<dim3(DD/128, TT*KX/128, 1), 256, TG_SMEM>>>(
        gS, sMid, 0, f2S, (size_t)DD*DD, 0, DD,
        nullptr, ao, ref, DD, 0, 0);
    // combine
    combine_kernel<<<2048, 256>>>(ref, tkp, comb);
    // output projection
    split3<<<1024, 256>>>(comb, gS, sSm, sSm);
    tgemm<<<dim3(DD/128, TT/128, 1), 256, TG_SMEM>>>(
        gS, sSm, 0, owS, (size_t)DD*DD, 0, DD,
        nullptr, nullptr, out, DD, 0, 0);
    // aux
    if (write_aux)
        aux_kernel<<<1, 256>>>(rprobs, ent, out + sSm);
}